// round 3
// baseline (speedup 1.0000x reference)
#include <cuda_runtime.h>
#include <cuda_bf16.h>
#include <math.h>
#include <stdint.h>

// Problem constants
#define B_   16
#define C_   512
#define NH_  8
#define HD_  64
#define N_   1024
#define QSCALE 0.125f

// ---------------------------------------------------------------------------
// Scratch (device globals: allocation-free rule)
// ---------------------------------------------------------------------------
__device__ float g_qkv[(size_t)3 * B_ * C_ * N_];   // [s][b][c][n] fp32 (Q pre-scaled)
__device__ float g_attn[(size_t)B_ * C_ * N_];      // [b][c][n] fp32

__device__ __nv_bfloat16 g_wqkv_hi[(size_t)3 * C_ * C_];
__device__ __nv_bfloat16 g_wqkv_lo[(size_t)3 * C_ * C_];
__device__ __nv_bfloat16 g_wproj_hi[(size_t)C_ * C_];
__device__ __nv_bfloat16 g_wproj_lo[(size_t)C_ * C_];
__device__ __nv_bfloat16 g_xt_hi[(size_t)B_ * N_ * C_];   // [b][n][c] K-major
__device__ __nv_bfloat16 g_xt_lo[(size_t)B_ * N_ * C_];
__device__ __nv_bfloat16 g_at_hi[(size_t)B_ * N_ * C_];
__device__ __nv_bfloat16 g_at_lo[(size_t)B_ * N_ * C_];

// ---------------------------------------------------------------------------
// Warp-level MMA helpers (arch-portable: sm_80+, works on plain sm_103 target)
// ---------------------------------------------------------------------------
__device__ __forceinline__ uint32_t smem_u32(const void* p) {
    uint32_t a;
    asm("{ .reg .u64 t; cvta.to.shared.u64 t, %1; cvt.u32.u64 %0, t; }" : "=r"(a) : "l"(p));
    return a;
}

#define LDMX4(R, saddr)                                                        \
    asm volatile("ldmatrix.sync.aligned.m8n8.x4.shared.b16 {%0,%1,%2,%3}, [%4];" \
        : "=r"((R)[0]), "=r"((R)[1]), "=r"((R)[2]), "=r"((R)[3]) : "r"(saddr))

__device__ __forceinline__ void mma16816(float* d, const uint32_t* a, const uint32_t* b) {
    asm volatile("mma.sync.aligned.m16n8k16.row.col.f32.bf16.bf16.f32 "
        "{%0,%1,%2,%3}, {%4,%5,%6,%7}, {%8,%9}, {%0,%1,%2,%3};"
        : "+f"(d[0]), "+f"(d[1]), "+f"(d[2]), "+f"(d[3])
        : "r"(a[0]), "r"(a[1]), "r"(a[2]), "r"(a[3]), "r"(b[0]), "r"(b[1]));
}

// ---------------------------------------------------------------------------
// Conversion kernels
// ---------------------------------------------------------------------------
__global__ void convert_w(const float* __restrict__ w, __nv_bfloat16* __restrict__ hi,
                          __nv_bfloat16* __restrict__ lo, int total, int qelems) {
    int i = blockIdx.x * 256 + threadIdx.x;
    if (i >= total) return;
    float v = w[i];
    if (i < qelems) v *= QSCALE;     // fold attention scale into Q weight rows
    __nv_bfloat16 h = __float2bfloat16(v);
    hi[i] = h;
    lo[i] = __float2bfloat16(v - __bfloat162float(h));
}

// in[b][c][n] fp32 -> out[b][n][c] bf16 hi/lo.  SRC=0: param, SRC=1: g_attn
template<int SRC>
__global__ __launch_bounds__(256)
void convert_xT(const float* __restrict__ xin, __nv_bfloat16* __restrict__ hi,
                __nv_bfloat16* __restrict__ lo) {
    __shared__ float t[32][33];
    const int n0 = blockIdx.x * 32, c0 = blockIdx.y * 32, b = blockIdx.z;
    const int tx = threadIdx.x, ty = threadIdx.y;
    const float* xb = (SRC == 1 ? g_attn : xin) + (size_t)b * C_ * N_;
    #pragma unroll
    for (int r = ty; r < 32; r += 8)
        t[r][tx] = xb[(size_t)(c0 + r) * N_ + n0 + tx];
    __syncthreads();
    #pragma unroll
    for (int r = ty; r < 32; r += 8) {
        float v = t[tx][r];
        size_t o = ((size_t)b * N_ + n0 + r) * C_ + c0 + tx;
        __nv_bfloat16 h = __float2bfloat16(v);
        hi[o] = h;
        lo[o] = __float2bfloat16(v - __bfloat162float(h));
    }
}

// ---------------------------------------------------------------------------
// mma.sync GEMM: D[o][n] = sum_c A[o][c]*B[n][c], bf16 hi/lo, fp32 acc.
// Block tile 128x128, BK=32, 256 threads (8 warps, 4x2), warp tile 32x64.
// smem rows padded to 40 bf16 (80B) -> ldmatrix phases hit 8 distinct bank
// groups ((5m+q) mod 8 is a permutation of 0..7).
// MODE 0: scatter into g_qkv.  MODE 1: +bias, write out.
// ---------------------------------------------------------------------------
#define SSTRIDE 40   // bf16 elems per smem row (32 data + 8 pad)

template<int MODE>
__global__ __launch_bounds__(256)
void gemm_mma(const __nv_bfloat16* __restrict__ Ahi, const __nv_bfloat16* __restrict__ Alo,
              const __nv_bfloat16* __restrict__ Bhi, const __nv_bfloat16* __restrict__ Blo,
              const float* __restrict__ bias, float* __restrict__ out)
{
    __shared__ __nv_bfloat16 sm[4][128 * SSTRIDE];   // Ah, Al, Bh, Bl

    const int b  = blockIdx.z;
    const int o0 = blockIdx.x * 128;
    const int n0 = blockIdx.y * 128;
    const int tid = threadIdx.x;
    const int wid = tid >> 5, lane = tid & 31;
    const int wm = wid >> 1, wn = wid & 1;           // 4 x 2 warp grid

    const __nv_bfloat16* srcs[4] = {
        Ahi + (size_t)o0 * C_,
        Alo + (size_t)o0 * C_,
        Bhi + ((size_t)b * N_ + n0) * C_,
        Blo + ((size_t)b * N_ + n0) * C_
    };

    float acc[2][8][4];
    #pragma unroll
    for (int i = 0; i < 2; i++)
        #pragma unroll
        for (int j = 0; j < 8; j++)
            #pragma unroll
            for (int k = 0; k < 4; k++) acc[i][j][k] = 0.f;

    const uint32_t smb = smem_u32(&sm[0][0]);
    // ldmatrix base offsets for this thread (row = lane&15, kchunk = lane>>4)
    const int lrow = lane & 15, lkc = lane >> 4;

    for (int kt = 0; kt < C_; kt += 32) {
        // global -> smem: 2048 uint4 over 256 threads
        #pragma unroll
        for (int it = 0; it < 8; it++) {
            int idx = it * 256 + tid;
            int mat = idx >> 9;
            int r   = idx & 511;
            int m   = r >> 2, q = r & 3;
            *(uint4*)&sm[mat][m * SSTRIDE + q * 8] =
                *(const uint4*)(srcs[mat] + (size_t)m * C_ + kt + q * 8);
        }
        __syncthreads();

        #pragma unroll
        for (int kb = 0; kb < 2; kb++) {
            uint32_t ah[2][4], al[2][4];
            #pragma unroll
            for (int mi = 0; mi < 2; mi++) {
                uint32_t off = ((wm * 32 + mi * 16 + lrow) * SSTRIDE + kb * 16 + lkc * 8) * 2;
                LDMX4(ah[mi], smb + 0 * (128 * SSTRIDE * 2) + off);
                LDMX4(al[mi], smb + 1 * (128 * SSTRIDE * 2) + off);
            }
            uint32_t bh[8][2], bl[8][2];
            #pragma unroll
            for (int nj = 0; nj < 4; nj++) {
                uint32_t off = ((wn * 64 + nj * 16 + lrow) * SSTRIDE + kb * 16 + lkc * 8) * 2;
                uint32_t r4[4];
                LDMX4(r4, smb + 2 * (128 * SSTRIDE * 2) + off);
                bh[nj * 2][0] = r4[0]; bh[nj * 2][1] = r4[2];
                bh[nj * 2 + 1][0] = r4[1]; bh[nj * 2 + 1][1] = r4[3];
                LDMX4(r4, smb + 3 * (128 * SSTRIDE * 2) + off);
                bl[nj * 2][0] = r4[0]; bl[nj * 2][1] = r4[2];
                bl[nj * 2 + 1][0] = r4[1]; bl[nj * 2 + 1][1] = r4[3];
            }
            #pragma unroll
            for (int mi = 0; mi < 2; mi++)
                #pragma unroll
                for (int ni = 0; ni < 8; ni++) {
                    mma16816(acc[mi][ni], ah[mi], bh[ni]);
                    mma16816(acc[mi][ni], ah[mi], bl[ni]);
                    mma16816(acc[mi][ni], al[mi], bh[ni]);
                }
        }
        __syncthreads();
    }

    // Epilogue: c0,c1 -> row lane/4, cols (lane%4)*2,+1 ; c2,c3 -> row+8
    const int r0 = lane >> 2, cidx = (lane & 3) * 2;
    #pragma unroll
    for (int mi = 0; mi < 2; mi++) {
        #pragma unroll
        for (int rh = 0; rh < 2; rh++) {
            int o = o0 + wm * 32 + mi * 16 + r0 + rh * 8;
            float bv = 0.f;
            float* dst;
            if (MODE == 0) {
                int s = o >> 9, rem = o & 511;
                dst = g_qkv + (((size_t)s * B_ + b) * C_ + rem) * N_ + n0 + wn * 64;
            } else {
                bv = bias[o];
                dst = out + ((size_t)b * C_ + o) * N_ + n0 + wn * 64;
            }
            #pragma unroll
            for (int nj = 0; nj < 8; nj++) {
                float2 v;
                v.x = acc[mi][nj][rh * 2 + 0] + bv;
                v.y = acc[mi][nj][rh * 2 + 1] + bv;
                *(float2*)(dst + nj * 8 + cidx) = v;
            }
        }
    }
}

// ---------------------------------------------------------------------------
// Flash attention (scalar): 1 thread = 1 query row.
// ---------------------------------------------------------------------------
__global__ __launch_bounds__(128)
void attn_kernel()
{
    const int bh = blockIdx.x;
    const int b  = bh >> 3, h = bh & 7;
    const int tid = threadIdx.x;
    const int n  = blockIdx.y * 128 + tid;

    __shared__ float Ks[64 * 64];   // [d][j]
    __shared__ float Vs[64 * 64];   // [d][j]

    const size_t headoff = ((size_t)b * C_ + h * HD_) * N_;
    const float* Qg = g_qkv + headoff;
    const float* Kg = g_qkv + (size_t)1 * B_ * C_ * N_ + headoff;
    const float* Vg = g_qkv + (size_t)2 * B_ * C_ * N_ + headoff;

    float q[64], o[64];
    #pragma unroll
    for (int d = 0; d < 64; d++) { q[d] = Qg[(size_t)d * N_ + n]; o[d] = 0.f; }

    float m = -INFINITY, l = 0.f;

    for (int t0 = 0; t0 < N_; t0 += 64) {
        for (int f = tid; f < 64 * 16; f += 128) {
            int d = f >> 4, j4 = (f & 15) * 4;
            *(float4*)&Ks[d * 64 + j4] = *(const float4*)&Kg[(size_t)d * N_ + t0 + j4];
            *(float4*)&Vs[d * 64 + j4] = *(const float4*)&Vg[(size_t)d * N_ + t0 + j4];
        }
        __syncthreads();

        for (int j4 = 0; j4 < 64; j4 += 4) {
            float s0 = 0.f, s1 = 0.f, s2 = 0.f, s3 = 0.f;
            #pragma unroll
            for (int d = 0; d < 64; d++) {
                float4 kk = *(const float4*)&Ks[d * 64 + j4];
                s0 += q[d] * kk.x; s1 += q[d] * kk.y;
                s2 += q[d] * kk.z; s3 += q[d] * kk.w;
            }
            float gm = fmaxf(fmaxf(s0, s1), fmaxf(s2, s3));
            if (gm > m) {
                float corr = __expf(m - gm);
                l *= corr;
                #pragma unroll
                for (int d = 0; d < 64; d++) o[d] *= corr;
                m = gm;
            }
            float p0 = __expf(s0 - m), p1 = __expf(s1 - m);
            float p2 = __expf(s2 - m), p3 = __expf(s3 - m);
            l += p0 + p1 + p2 + p3;
            #pragma unroll
            for (int d = 0; d < 64; d++) {
                float4 vv = *(const float4*)&Vs[d * 64 + j4];
                o[d] += p0 * vv.x + p1 * vv.y + p2 * vv.z + p3 * vv.w;
            }
        }
        __syncthreads();
    }

    const float inv = 1.f / l;
    float* Og = g_attn + headoff;
    #pragma unroll
    for (int d = 0; d < 64; d++)
        Og[(size_t)d * N_ + n] = o[d] * inv;
}

// ---------------------------------------------------------------------------
extern "C" void kernel_launch(void* const* d_in, const int* in_sizes, int n_in,
                              void* d_out, int out_size)
{
    const float* x      = (const float*)d_in[0];   // [B, C, H, W]
    const float* w_qkv  = (const float*)d_in[1];   // [3C, C]
    const float* w_proj = (const float*)d_in[2];   // [C, C]
    const float* b_proj = (const float*)d_in[3];   // [C]
    float* out = (float*)d_out;

    // 1) weight conversion (Q rows pre-scaled by HD^-0.5)
    convert_w<<<(3 * C_ * C_ + 255) / 256, 256>>>(w_qkv, g_wqkv_hi, g_wqkv_lo,
                                                  3 * C_ * C_, C_ * C_);
    convert_w<<<(C_ * C_ + 255) / 256, 256>>>(w_proj, g_wproj_hi, g_wproj_lo,
                                              C_ * C_, 0);
    // 2) X transpose+convert: [b][c][n] -> [b][n][c] bf16 hi/lo
    convert_xT<0><<<dim3(N_ / 32, C_ / 32, B_), dim3(32, 8)>>>(x, g_xt_hi, g_xt_lo);

    // 3) QKV GEMM (mma.sync)
    gemm_mma<0><<<dim3(3 * C_ / 128, N_ / 128, B_), 256>>>(
        g_wqkv_hi, g_wqkv_lo, g_xt_hi, g_xt_lo, nullptr, nullptr);

    // 4) attention (scalar flash)
    attn_kernel<<<dim3(B_ * NH_, N_ / 128), 128>>>();

    // 5) attention output transpose+convert
    convert_xT<1><<<dim3(N_ / 32, C_ / 32, B_), dim3(32, 8)>>>(nullptr, g_at_hi, g_at_lo);

    // 6) proj GEMM (mma.sync) + bias
    gemm_mma<1><<<dim3(C_ / 128, N_ / 128, B_), 256>>>(
        g_wproj_hi, g_wproj_lo, g_at_hi, g_at_lo, b_proj, out);
}

// round 8
// speedup vs baseline: 1.2376x; 1.2376x over previous
#include <cuda_runtime.h>
#include <cuda_bf16.h>
#include <math.h>
#include <stdint.h>

// Problem constants
#define B_   16
#define C_   512
#define NH_  8
#define HD_  64
#define N_   1024
#define QSCALE 0.125f

// ---------------------------------------------------------------------------
// Scratch (device globals) — same layout classes as passing R1/R3 rounds.
// ---------------------------------------------------------------------------
__device__ float g_qkv[(size_t)3 * B_ * C_ * N_];   // [s][b][c][n] fp32 (Q pre-scaled)
__device__ float g_attn[(size_t)B_ * C_ * N_];      // [b][c][n] fp32

__device__ __nv_bfloat16 g_wqkv_hi[(size_t)3 * C_ * C_];
__device__ __nv_bfloat16 g_wqkv_lo[(size_t)3 * C_ * C_];
__device__ __nv_bfloat16 g_xt_hi[(size_t)B_ * N_ * C_];   // [b][n][c]
__device__ __nv_bfloat16 g_xt_lo[(size_t)B_ * N_ * C_];

// ---------------------------------------------------------------------------
// Warp-level MMA helpers (R3-validated)
// ---------------------------------------------------------------------------
__device__ __forceinline__ uint32_t smem_u32(const void* p) {
    uint32_t a;
    asm("{ .reg .u64 t; cvta.to.shared.u64 t, %1; cvt.u32.u64 %0, t; }" : "=r"(a) : "l"(p));
    return a;
}

#define LDMX4(R, saddr)                                                        \
    asm volatile("ldmatrix.sync.aligned.m8n8.x4.shared.b16 {%0,%1,%2,%3}, [%4];" \
        : "=r"((R)[0]), "=r"((R)[1]), "=r"((R)[2]), "=r"((R)[3]) : "r"(saddr))

__device__ __forceinline__ void mma16816(float* d, const uint32_t* a, const uint32_t* b) {
    asm volatile("mma.sync.aligned.m16n8k16.row.col.f32.bf16.bf16.f32 "
        "{%0,%1,%2,%3}, {%4,%5,%6,%7}, {%8,%9}, {%0,%1,%2,%3};"
        : "+f"(d[0]), "+f"(d[1]), "+f"(d[2]), "+f"(d[3])
        : "r"(a[0]), "r"(a[1]), "r"(a[2]), "r"(a[3]), "r"(b[0]), "r"(b[1]));
}

// ---------------------------------------------------------------------------
// Conversion kernels (R3 verbatim)
// ---------------------------------------------------------------------------
__global__ void convert_w(const float* __restrict__ w, __nv_bfloat16* __restrict__ hi,
                          __nv_bfloat16* __restrict__ lo, int total, int qelems) {
    int i = blockIdx.x * 256 + threadIdx.x;
    if (i >= total) return;
    float v = w[i];
    if (i < qelems) v *= QSCALE;     // fold attention scale into Q weight rows
    __nv_bfloat16 h = __float2bfloat16(v);
    hi[i] = h;
    lo[i] = __float2bfloat16(v - __bfloat162float(h));
}

// in[b][c][n] fp32 -> out[b][n][c] bf16 hi/lo
template<int SRC>
__global__ __launch_bounds__(256)
void convert_xT(const float* __restrict__ xin, __nv_bfloat16* __restrict__ hi,
                __nv_bfloat16* __restrict__ lo) {
    __shared__ float t[32][33];
    const int n0 = blockIdx.x * 32, c0 = blockIdx.y * 32, b = blockIdx.z;
    const int tx = threadIdx.x, ty = threadIdx.y;
    const float* xb = (SRC == 1 ? g_attn : xin) + (size_t)b * C_ * N_;
    #pragma unroll
    for (int r = ty; r < 32; r += 8)
        t[r][tx] = xb[(size_t)(c0 + r) * N_ + n0 + tx];
    __syncthreads();
    #pragma unroll
    for (int r = ty; r < 32; r += 8) {
        float v = t[tx][r];
        size_t o = ((size_t)b * N_ + n0 + r) * C_ + c0 + tx;
        __nv_bfloat16 h = __float2bfloat16(v);
        hi[o] = h;
        lo[o] = __float2bfloat16(v - __bfloat162float(h));
    }
}

// ---------------------------------------------------------------------------
// R3-validated HMMA GEMM: D[o][n] = sum_c A[o][c]*B[n][c], hi/lo, fp32 acc.
// MODE 0 only here: scatter fp32 into g_qkv (Q pre-scaled via weights).
// ---------------------------------------------------------------------------
#define SSTRIDE 40

template<int MODE>
__global__ __launch_bounds__(256)
void gemm_mma(const __nv_bfloat16* __restrict__ Ahi, const __nv_bfloat16* __restrict__ Alo,
              const __nv_bfloat16* __restrict__ Bhi, const __nv_bfloat16* __restrict__ Blo,
              const float* __restrict__ bias, float* __restrict__ out)
{
    __shared__ __nv_bfloat16 sm[4][128 * SSTRIDE];

    const int b  = blockIdx.z;
    const int o0 = blockIdx.x * 128;
    const int n0 = blockIdx.y * 128;
    const int tid = threadIdx.x;
    const int wid = tid >> 5, lane = tid & 31;
    const int wm = wid >> 1, wn = wid & 1;

    const __nv_bfloat16* srcs[4] = {
        Ahi + (size_t)o0 * C_,
        Alo + (size_t)o0 * C_,
        Bhi + ((size_t)b * N_ + n0) * C_,
        Blo + ((size_t)b * N_ + n0) * C_
    };

    float acc[2][8][4];
    #pragma unroll
    for (int i = 0; i < 2; i++)
        #pragma unroll
        for (int j = 0; j < 8; j++)
            #pragma unroll
            for (int k = 0; k < 4; k++) acc[i][j][k] = 0.f;

    const uint32_t smb = smem_u32(&sm[0][0]);
    const int lrow = lane & 15, lkc = lane >> 4;

    for (int kt = 0; kt < C_; kt += 32) {
        #pragma unroll
        for (int it = 0; it < 8; it++) {
            int idx = it * 256 + tid;
            int mat = idx >> 9;
            int r   = idx & 511;
            int m   = r >> 2, q = r & 3;
            *(uint4*)&sm[mat][m * SSTRIDE + q * 8] =
                *(const uint4*)(srcs[mat] + (size_t)m * C_ + kt + q * 8);
        }
        __syncthreads();

        #pragma unroll
        for (int kb = 0; kb < 2; kb++) {
            uint32_t ah[2][4], al[2][4];
            #pragma unroll
            for (int mi = 0; mi < 2; mi++) {
                uint32_t off = ((wm * 32 + mi * 16 + lrow) * SSTRIDE + kb * 16 + lkc * 8) * 2;
                LDMX4(ah[mi], smb + 0 * (128 * SSTRIDE * 2) + off);
                LDMX4(al[mi], smb + 1 * (128 * SSTRIDE * 2) + off);
            }
            uint32_t bh[8][2], bl[8][2];
            #pragma unroll
            for (int nj = 0; nj < 4; nj++) {
                uint32_t off = ((wn * 64 + nj * 16 + lrow) * SSTRIDE + kb * 16 + lkc * 8) * 2;
                uint32_t r4[4];
                LDMX4(r4, smb + 2 * (128 * SSTRIDE * 2) + off);
                bh[nj * 2][0] = r4[0]; bh[nj * 2][1] = r4[2];
                bh[nj * 2 + 1][0] = r4[1]; bh[nj * 2 + 1][1] = r4[3];
                LDMX4(r4, smb + 3 * (128 * SSTRIDE * 2) + off);
                bl[nj * 2][0] = r4[0]; bl[nj * 2][1] = r4[2];
                bl[nj * 2 + 1][0] = r4[1]; bl[nj * 2 + 1][1] = r4[3];
            }
            #pragma unroll
            for (int mi = 0; mi < 2; mi++)
                #pragma unroll
                for (int ni = 0; ni < 8; ni++) {
                    mma16816(acc[mi][ni], ah[mi], bh[ni]);
                    mma16816(acc[mi][ni], ah[mi], bl[ni]);
                    mma16816(acc[mi][ni], al[mi], bh[ni]);
                }
        }
        __syncthreads();
    }

    const int r0 = lane >> 2, cidx = (lane & 3) * 2;
    #pragma unroll
    for (int mi = 0; mi < 2; mi++) {
        #pragma unroll
        for (int rh = 0; rh < 2; rh++) {
            int o = o0 + wm * 32 + mi * 16 + r0 + rh * 8;
            float bv = 0.f;
            float* dst;
            if (MODE == 0) {
                int s = o >> 9, rem = o & 511;
                dst = g_qkv + (((size_t)s * B_ + b) * C_ + rem) * N_ + n0 + wn * 64;
            } else {
                bv = bias[o];
                dst = out + ((size_t)b * C_ + o) * N_ + n0 + wn * 64;
            }
            #pragma unroll
            for (int nj = 0; nj < 8; nj++) {
                float2 v;
                v.x = acc[mi][nj][rh * 2 + 0] + bv;
                v.y = acc[mi][nj][rh * 2 + 1] + bv;
                *(float2*)(dst + nj * 8 + cidx) = v;
            }
        }
    }
}

// ---------------------------------------------------------------------------
// R1-validated scalar GEMM: out[b][o][n] = sum_c W[o][c] * X[b][c][n]
// MODE 1: read g_attn, add bias, write out. (fp32 weights direct from input)
// ---------------------------------------------------------------------------
template<int MODE>
__global__ __launch_bounds__(256)
void gemm_kernel(const float* __restrict__ W, const float* __restrict__ Xin,
                 const float* __restrict__ bias, float* __restrict__ out)
{
    const int b  = blockIdx.z;
    const int o0 = blockIdx.x * 64;
    const int n0 = blockIdx.y * 64;
    const int tid = threadIdx.x;
    const int tx = tid & 15, ty = tid >> 4;

    __shared__ float Ws[16][64];   // [k][m]
    __shared__ float Xs[16][64];   // [k][j]

    const float* Xb = (MODE == 1 ? g_attn : Xin) + (size_t)b * C_ * N_;

    float acc[4][4];
    #pragma unroll
    for (int i = 0; i < 4; i++)
        #pragma unroll
        for (int j = 0; j < 4; j++) acc[i][j] = 0.f;

    for (int kt = 0; kt < C_; kt += 16) {
        #pragma unroll
        for (int r = 0; r < 4; r++) {
            int idx = tid + r * 256;
            int m = idx >> 4, k = idx & 15;
            Ws[k][m] = W[(size_t)(o0 + m) * C_ + kt + k];
        }
        #pragma unroll
        for (int r = 0; r < 4; r++) {
            int idx = tid + r * 256;
            int k = idx >> 6, j = idx & 63;
            Xs[k][j] = Xb[(size_t)(kt + k) * N_ + n0 + j];
        }
        __syncthreads();

        #pragma unroll
        for (int k = 0; k < 16; k++) {
            float4 a4 = *(const float4*)&Ws[k][ty * 4];
            float4 x4 = *(const float4*)&Xs[k][tx * 4];
            float av[4] = {a4.x, a4.y, a4.z, a4.w};
            float xv[4] = {x4.x, x4.y, x4.z, x4.w};
            #pragma unroll
            for (int i = 0; i < 4; i++)
                #pragma unroll
                for (int j = 0; j < 4; j++)
                    acc[i][j] += av[i] * xv[j];
        }
        __syncthreads();
    }

    #pragma unroll
    for (int i = 0; i < 4; i++) {
        int o = o0 + ty * 4 + i;
        #pragma unroll
        for (int j = 0; j < 4; j++) {
            int n = n0 + tx * 4 + j;
            float v = acc[i][j];
            if (MODE == 0) {
                int s   = o >> 9;
                int rem = o & 511;
                if (s == 0) v *= QSCALE;
                g_qkv[(((size_t)s * B_ + b) * C_ + rem) * N_ + n] = v;
            } else {
                out[((size_t)b * C_ + o) * N_ + n] = v + bias[o];
            }
        }
    }
}

// ---------------------------------------------------------------------------
// R1-validated scalar flash attention: 1 thread = 1 query row.
// ---------------------------------------------------------------------------
__global__ __launch_bounds__(128)
void attn_kernel()
{
    const int bh = blockIdx.x;
    const int b  = bh >> 3, h = bh & 7;
    const int tid = threadIdx.x;
    const int n  = blockIdx.y * 128 + tid;

    __shared__ float Ks[64 * 64];   // [d][j]
    __shared__ float Vs[64 * 64];   // [d][j]

    const size_t headoff = ((size_t)b * C_ + h * HD_) * N_;
    const float* Qg = g_qkv + headoff;                               // s=0 (pre-scaled)
    const float* Kg = g_qkv + (size_t)1 * B_ * C_ * N_ + headoff;    // s=1
    const float* Vg = g_qkv + (size_t)2 * B_ * C_ * N_ + headoff;    // s=2

    float q[64], o[64];
    #pragma unroll
    for (int d = 0; d < 64; d++) { q[d] = Qg[(size_t)d * N_ + n]; o[d] = 0.f; }

    float m = -INFINITY, l = 0.f;

    for (int t0 = 0; t0 < N_; t0 += 64) {
        for (int f = tid; f < 64 * 16; f += 128) {
            int d = f >> 4, j4 = (f & 15) * 4;
            *(float4*)&Ks[d * 64 + j4] = *(const float4*)&Kg[(size_t)d * N_ + t0 + j4];
            *(float4*)&Vs[d * 64 + j4] = *(const float4*)&Vg[(size_t)d * N_ + t0 + j4];
        }
        __syncthreads();

        for (int j4 = 0; j4 < 64; j4 += 4) {
            float s0 = 0.f, s1 = 0.f, s2 = 0.f, s3 = 0.f;
            #pragma unroll
            for (int d = 0; d < 64; d++) {
                float4 kk = *(const float4*)&Ks[d * 64 + j4];
                s0 += q[d] * kk.x; s1 += q[d] * kk.y;
                s2 += q[d] * kk.z; s3 += q[d] * kk.w;
            }
            float gm = fmaxf(fmaxf(s0, s1), fmaxf(s2, s3));
            if (gm > m) {
                float corr = __expf(m - gm);
                l *= corr;
                #pragma unroll
                for (int d = 0; d < 64; d++) o[d] *= corr;
                m = gm;
            }
            float p0 = __expf(s0 - m), p1 = __expf(s1 - m);
            float p2 = __expf(s2 - m), p3 = __expf(s3 - m);
            l += p0 + p1 + p2 + p3;
            #pragma unroll
            for (int d = 0; d < 64; d++) {
                float4 vv = *(const float4*)&Vs[d * 64 + j4];
                o[d] += p0 * vv.x + p1 * vv.y + p2 * vv.z + p3 * vv.w;
            }
        }
        __syncthreads();
    }

    const float inv = 1.f / l;
    float* Og = g_attn + headoff;
    #pragma unroll
    for (int d = 0; d < 64; d++)
        Og[(size_t)d * N_ + n] = o[d] * inv;
}

// ---------------------------------------------------------------------------
extern "C" void kernel_launch(void* const* d_in, const int* in_sizes, int n_in,
                              void* d_out, int out_size)
{
    const float* x      = (const float*)d_in[0];   // [B, C, H, W]
    const float* w_qkv  = (const float*)d_in[1];   // [3C, C]
    const float* w_proj = (const float*)d_in[2];   // [C, C]
    const float* b_proj = (const float*)d_in[3];   // [C]
    float* out = (float*)d_out;

    // 1) qkv weight conversion (Q rows pre-scaled by HD^-0.5)   [R3-proven]
    convert_w<<<(3 * C_ * C_ + 255) / 256, 256>>>(w_qkv, g_wqkv_hi, g_wqkv_lo,
                                                  3 * C_ * C_, C_ * C_);
    // 2) X transpose+convert: [b][c][n] -> [b][n][c] bf16 hi/lo [R3-proven]
    convert_xT<0><<<dim3(N_ / 32, C_ / 32, B_), dim3(32, 8)>>>(x, g_xt_hi, g_xt_lo);

    // 3) QKV GEMM (HMMA hi/lo) -> fp32 g_qkv                    [R3-proven]
    gemm_mma<0><<<dim3(3 * C_ / 128, N_ / 128, B_), 256>>>(
        g_wqkv_hi, g_wqkv_lo, g_xt_hi, g_xt_lo, nullptr, nullptr);

    // 4) scalar flash attention -> fp32 g_attn                  [R1/R3-proven]
    attn_kernel<<<dim3(B_ * NH_, N_ / 128), 128>>>();

    // 5) proj GEMM (scalar) + bias -> fp32 out                  [R1-proven]
    gemm_kernel<1><<<dim3(C_ / 64, N_ / 64, B_), 256>>>(w_proj, nullptr, b_proj, out);
}

// round 9
// speedup vs baseline: 4.9574x; 4.0057x over previous
#include <cuda_runtime.h>
#include <math.h>
#include <stdint.h>

// Problem constants
#define B_   16
#define C_   512
#define NH_  8
#define HD_  64
#define N_   1024
#define QSCALE 0.125f

typedef unsigned long long ull;

// ---------------------------------------------------------------------------
// Scratch (device globals) — pure fp32 pipeline, no conversions.
// ---------------------------------------------------------------------------
__device__ float g_qkv[(size_t)3 * B_ * C_ * N_];   // [s][b][c][n] (Q pre-scaled)
__device__ float g_attn[(size_t)B_ * C_ * N_];      // [b][c][n]

// ---------------------------------------------------------------------------
// Packed f32x2 helpers (sm_100+ family PTX, not an 'a' feature)
// ---------------------------------------------------------------------------
__device__ __forceinline__ ull pk2(float x, float y) {
    ull r;
    asm("mov.b64 %0, {%1, %2};"
        : "=l"(r) : "r"(__float_as_uint(x)), "r"(__float_as_uint(y)));
    return r;
}
__device__ __forceinline__ void up2(ull v, float& x, float& y) {
    uint32_t a, b;
    asm("mov.b64 {%0, %1}, %2;" : "=r"(a), "=r"(b) : "l"(v));
    x = __uint_as_float(a); y = __uint_as_float(b);
}
__device__ __forceinline__ ull fma2(ull a, ull b, ull c) {
    ull d;
    asm("fma.rn.f32x2 %0, %1, %2, %3;" : "=l"(d) : "l"(a), "l"(b), "l"(c));
    return d;
}
__device__ __forceinline__ ull mul2(ull a, ull b) {
    ull d;
    asm("mul.rn.f32x2 %0, %1, %2;" : "=l"(d) : "l"(a), "l"(b));
    return d;
}

// ---------------------------------------------------------------------------
// f32x2 GEMM: D[o][n] = sum_c W[o][c] * X[b][c][n].
// Block 128(o) x 128(n), BK=16, 256 threads (16x16), 8x8 micro-tile.
// acc packed over n-pairs; A stored in smem as duplicated (v,v) ull so the
// inner loop is LDS + fma2 only (no per-iteration packing movs).
// MODE 0: scatter fp32 into g_qkv (Q rows scaled by QSCALE).
// MODE 1: read g_attn as B, add bias, write fp32 out.
// ---------------------------------------------------------------------------
template<int MODE>
__global__ __launch_bounds__(256)
void gemm_f32x2(const float* __restrict__ W, const float* __restrict__ Xin,
                const float* __restrict__ bias, float* __restrict__ out)
{
    __shared__ ull   As2[16][128];   // [k][o], each entry = (a, a)   (16 KB)
    __shared__ float Bs[16][128];    // [k][n]                         (8 KB)

    const int b  = blockIdx.z;
    const int o0 = blockIdx.x * 128;
    const int n0 = blockIdx.y * 128;
    const int tid = threadIdx.x;
    const int tx = tid & 15, ty = tid >> 4;

    const float* Xb = (MODE == 1 ? g_attn : Xin) + (size_t)b * C_ * N_;

    ull acc[8][4];
    #pragma unroll
    for (int i = 0; i < 8; i++)
        #pragma unroll
        for (int j = 0; j < 4; j++) acc[i][j] = 0ull;

    for (int kt = 0; kt < C_; kt += 16) {
        // A: 128 o x 16 k, duplicated into ull pairs
        #pragma unroll
        for (int r = 0; r < 2; r++) {
            int idx = tid + r * 256;           // 0..511 float4 units
            int m = idx >> 2, q = idx & 3;
            float4 a4 = *(const float4*)&W[(size_t)(o0 + m) * C_ + kt + q * 4];
            As2[q * 4 + 0][m] = pk2(a4.x, a4.x);
            As2[q * 4 + 1][m] = pk2(a4.y, a4.y);
            As2[q * 4 + 2][m] = pk2(a4.z, a4.z);
            As2[q * 4 + 3][m] = pk2(a4.w, a4.w);
        }
        // B: 16 k x 128 n
        #pragma unroll
        for (int r = 0; r < 2; r++) {
            int idx = tid + r * 256;           // 0..511 float4 units
            int k = idx >> 5, j4 = idx & 31;
            *(float4*)&Bs[k][j4 * 4] =
                *(const float4*)&Xb[(size_t)(kt + k) * N_ + n0 + j4 * 4];
        }
        __syncthreads();

        #pragma unroll
        for (int k = 0; k < 16; k++) {
            ull aa[8];
            #pragma unroll
            for (int i = 0; i < 8; i++) aa[i] = As2[k][ty * 8 + i];
            ulonglong2 b20 = *(const ulonglong2*)&Bs[k][tx * 8];
            ulonglong2 b21 = *(const ulonglong2*)&Bs[k][tx * 8 + 4];
            ull b2[4] = { b20.x, b20.y, b21.x, b21.y };
            #pragma unroll
            for (int i = 0; i < 8; i++)
                #pragma unroll
                for (int j = 0; j < 4; j++)
                    acc[i][j] = fma2(aa[i], b2[j], acc[i][j]);
        }
        __syncthreads();
    }

    #pragma unroll
    for (int i = 0; i < 8; i++) {
        int o = o0 + ty * 8 + i;
        float scale = 1.f, bv = 0.f;
        float* dst;
        if (MODE == 0) {
            int s = o >> 9, rem = o & 511;
            if (s == 0) scale = QSCALE;
            dst = g_qkv + (((size_t)s * B_ + b) * C_ + rem) * N_ + n0;
        } else {
            bv = bias[o];
            dst = out + ((size_t)b * C_ + o) * N_ + n0;
        }
        #pragma unroll
        for (int j = 0; j < 4; j++) {
            float x, y;
            up2(acc[i][j], x, y);
            float2 v;
            if (MODE == 0) { v.x = x * scale; v.y = y * scale; }
            else           { v.x = x + bv;    v.y = y + bv; }
            *(float2*)(dst + tx * 8 + j * 2) = v;
        }
    }
}

// ---------------------------------------------------------------------------
// f32x2 flash attention: 1 thread = 1 query (R1-proven structure).
// K,V tiles transposed to [j][d] in smem (row stride 68 -> 16B-aligned rows,
// conflict-light transposed stores, broadcast LDS.128 reads).
// q and o live as packed d-pair (f32x2) registers.
// ---------------------------------------------------------------------------
__global__ __launch_bounds__(128)
void attn_f32x2()
{
    __shared__ float Ks[64][68];
    __shared__ float Vs[64][68];

    const int bh = blockIdx.x;
    const int b  = bh >> 3, h = bh & 7;
    const int tid = threadIdx.x;
    const int n  = blockIdx.y * 128 + tid;

    const size_t headoff = ((size_t)b * C_ + h * HD_) * N_;
    const float* Qg = g_qkv + headoff;                               // pre-scaled
    const float* Kg = g_qkv + (size_t)1 * B_ * C_ * N_ + headoff;
    const float* Vg = g_qkv + (size_t)2 * B_ * C_ * N_ + headoff;

    ull q2[32], o2[32];
    #pragma unroll
    for (int dp = 0; dp < 32; dp++) {
        q2[dp] = pk2(Qg[(size_t)(2 * dp) * N_ + n], Qg[(size_t)(2 * dp + 1) * N_ + n]);
        o2[dp] = 0ull;
    }
    float m = -INFINITY, l = 0.f;

    for (int t0 = 0; t0 < N_; t0 += 64) {
        // transposed tile loads: gmem [d][n] -> smem [j][d]
        #pragma unroll
        for (int it = 0; it < 8; it++) {
            int f = it * 128 + tid;        // 0..1023
            int d = f >> 4, j4 = f & 15;
            float4 kk = *(const float4*)&Kg[(size_t)d * N_ + t0 + j4 * 4];
            Ks[j4 * 4 + 0][d] = kk.x; Ks[j4 * 4 + 1][d] = kk.y;
            Ks[j4 * 4 + 2][d] = kk.z; Ks[j4 * 4 + 3][d] = kk.w;
            float4 vv = *(const float4*)&Vg[(size_t)d * N_ + t0 + j4 * 4];
            Vs[j4 * 4 + 0][d] = vv.x; Vs[j4 * 4 + 1][d] = vv.y;
            Vs[j4 * 4 + 2][d] = vv.z; Vs[j4 * 4 + 3][d] = vv.w;
        }
        __syncthreads();

        for (int j4 = 0; j4 < 16; j4++) {
            // scores for 4 keys
            float s[4];
            #pragma unroll
            for (int jj = 0; jj < 4; jj++) {
                const ulonglong2* kp = (const ulonglong2*)&Ks[j4 * 4 + jj][0];
                ull sa = 0ull, sb = 0ull;           // 2 chains for ILP
                #pragma unroll
                for (int dq = 0; dq < 16; dq++) {
                    ulonglong2 k2 = kp[dq];         // broadcast LDS.128
                    sa = fma2(q2[2 * dq],     k2.x, sa);
                    sb = fma2(q2[2 * dq + 1], k2.y, sb);
                }
                float ax, ay, bx, by;
                up2(sa, ax, ay); up2(sb, bx, by);
                s[jj] = (ax + bx) + (ay + by);
            }

            // online softmax (lazy rescale)
            float gm = fmaxf(fmaxf(s[0], s[1]), fmaxf(s[2], s[3]));
            if (gm > m) {
                float corr = __expf(m - gm);        // exp(-inf)=0 first tile
                l *= corr;
                ull cc = pk2(corr, corr);
                #pragma unroll
                for (int dp = 0; dp < 32; dp++) o2[dp] = mul2(o2[dp], cc);
                m = gm;
            }
            float p[4];
            #pragma unroll
            for (int jj = 0; jj < 4; jj++) { p[jj] = __expf(s[jj] - m); l += p[jj]; }

            // PV accumulate
            #pragma unroll
            for (int jj = 0; jj < 4; jj++) {
                ull pp = pk2(p[jj], p[jj]);
                const ulonglong2* vp = (const ulonglong2*)&Vs[j4 * 4 + jj][0];
                #pragma unroll
                for (int dq = 0; dq < 16; dq++) {
                    ulonglong2 v2 = vp[dq];         // broadcast LDS.128
                    o2[2 * dq]     = fma2(pp, v2.x, o2[2 * dq]);
                    o2[2 * dq + 1] = fma2(pp, v2.y, o2[2 * dq + 1]);
                }
            }
        }
        __syncthreads();
    }

    const float inv = 1.f / l;
    float* Og = g_attn + headoff;
    #pragma unroll
    for (int dp = 0; dp < 32; dp++) {
        float x, y;
        up2(o2[dp], x, y);
        Og[(size_t)(2 * dp) * N_ + n]     = x * inv;   // coalesced per d
        Og[(size_t)(2 * dp + 1) * N_ + n] = y * inv;
    }
}

// ---------------------------------------------------------------------------
extern "C" void kernel_launch(void* const* d_in, const int* in_sizes, int n_in,
                              void* d_out, int out_size)
{
    const float* x      = (const float*)d_in[0];   // [B, C, H, W]
    const float* w_qkv  = (const float*)d_in[1];   // [3C, C]
    const float* w_proj = (const float*)d_in[2];   // [C, C]
    const float* b_proj = (const float*)d_in[3];   // [C]
    float* out = (float*)d_out;

    // 1) QKV GEMM (f32x2) -> g_qkv, Q scaled
    gemm_f32x2<0><<<dim3(3 * C_ / 128, N_ / 128, B_), 256>>>(w_qkv, x, nullptr, nullptr);

    // 2) flash attention (f32x2) -> g_attn
    attn_f32x2<<<dim3(B_ * NH_, N_ / 128), 128>>>();

    // 3) proj GEMM (f32x2) + bias -> out
    gemm_f32x2<1><<<dim3(C_ / 128, N_ / 128, B_), 256>>>(w_proj, nullptr, b_proj, out);
}